// round 1
// baseline (speedup 1.0000x reference)
#include <cuda_runtime.h>
#include <math.h>

// Problem shapes (fixed by the dataset)
#define BB 8
#define NN 2048
#define MM 2048
#define DD 256

// Tiling
#define BN 128      // src rows per CTA
#define BM 128      // dst cols per m-tile
#define KT 32       // K chunk
#define NTHREADS 256
#define EPSV 1e-8f

// Norm scratch (no cudaMalloc allowed)
__device__ float g_xn[BB * NN];
__device__ float g_yn[BB * MM];

// One warp per descriptor row: L2-norm over D=256.
__global__ void norms_kernel(const float* __restrict__ src,
                             const float* __restrict__ dst) {
    int warp = (blockIdx.x * blockDim.x + threadIdx.x) >> 5;
    int lane = threadIdx.x & 31;
    const float* p;
    float* o;
    int row;
    if (warp < BB * NN) { p = src; o = g_xn; row = warp; }
    else                { p = dst; o = g_yn; row = warp - BB * NN; }
    const float4* v = (const float4*)(p + (size_t)row * DD) + lane * 2;
    float4 a = v[0], b4 = v[1];
    float s = a.x*a.x + a.y*a.y + a.z*a.z + a.w*a.w
            + b4.x*b4.x + b4.y*b4.y + b4.z*b4.z + b4.w*b4.w;
    #pragma unroll
    for (int off = 16; off; off >>= 1)
        s += __shfl_xor_sync(0xffffffffu, s, off);
    if (lane == 0) o[row] = sqrtf(s);
}

// Fused GEMM + cosine + argmax + gather.
// CTA: 128 src rows (blockIdx.x), batch = blockIdx.y. Sweeps all M in 128-col tiles.
// Thread (tx,ty) = (tid&15, tid>>4) owns an 8x8 microtile.
__global__ __launch_bounds__(NTHREADS)
void match_kernel(const float* __restrict__ src,
                  const float* __restrict__ dst,
                  const float* __restrict__ pts,
                  float* __restrict__ out) {
    // K-transposed tiles; stride BN+4=132 (16B-aligned rows, <=4-way STS conflicts,
    // conflict-free LDS since k is warp-uniform in the inner loop).
    __shared__ float As[KT][BN + 4];
    __shared__ float Bs[KT][BM + 4];

    const int b   = blockIdx.y;
    const int n0  = blockIdx.x * BN;
    const int tid = threadIdx.x;
    const int tx  = tid & 15;
    const int ty  = tid >> 4;

    const float* srcB = src + (size_t)b * NN * DD;
    const float* dstB = dst + (size_t)b * MM * DD;

    float best[8];
    int   bidx[8];
    #pragma unroll
    for (int r = 0; r < 8; r++) { best[r] = -1e30f; bidx[r] = 0; }

    float xn[8];
    #pragma unroll
    for (int r = 0; r < 8; r++) xn[r] = g_xn[b * NN + n0 + ty * 8 + r];

    for (int m0 = 0; m0 < MM; m0 += BM) {
        float acc[8][8];
        #pragma unroll
        for (int r = 0; r < 8; r++)
            #pragma unroll
            for (int c = 0; c < 8; c++) acc[r][c] = 0.0f;

        for (int kt = 0; kt < DD; kt += KT) {
            // Load A chunk: 128 rows x 32 k, coalesced 128B per row-group,
            // stored transposed As[k][row].
            #pragma unroll
            for (int i = 0; i < 4; i++) {
                int lin = tid + i * NTHREADS;     // 0..1023 float4 slots
                int row = lin >> 3;               // 8 float4 per row
                int k4  = lin & 7;
                float4 v = *(const float4*)(srcB + (size_t)(n0 + row) * DD + kt + k4 * 4);
                As[k4 * 4 + 0][row] = v.x;
                As[k4 * 4 + 1][row] = v.y;
                As[k4 * 4 + 2][row] = v.z;
                As[k4 * 4 + 3][row] = v.w;
            }
            // Load B chunk likewise.
            #pragma unroll
            for (int i = 0; i < 4; i++) {
                int lin = tid + i * NTHREADS;
                int row = lin >> 3;
                int k4  = lin & 7;
                float4 v = *(const float4*)(dstB + (size_t)(m0 + row) * DD + kt + k4 * 4);
                Bs[k4 * 4 + 0][row] = v.x;
                Bs[k4 * 4 + 1][row] = v.y;
                Bs[k4 * 4 + 2][row] = v.z;
                Bs[k4 * 4 + 3][row] = v.w;
            }
            __syncthreads();

            #pragma unroll 8
            for (int k = 0; k < KT; k++) {
                float4 a0 = *(const float4*)&As[k][ty * 8];
                float4 a1 = *(const float4*)&As[k][ty * 8 + 4];
                float4 b0 = *(const float4*)&Bs[k][tx * 8];
                float4 b1 = *(const float4*)&Bs[k][tx * 8 + 4];
                float av[8] = {a0.x, a0.y, a0.z, a0.w, a1.x, a1.y, a1.z, a1.w};
                float bv[8] = {b0.x, b0.y, b0.z, b0.w, b1.x, b1.y, b1.z, b1.w};
                #pragma unroll
                for (int r = 0; r < 8; r++)
                    #pragma unroll
                    for (int c = 0; c < 8; c++)
                        acc[r][c] = fmaf(av[r], bv[c], acc[r][c]);
            }
            __syncthreads();
        }

        // Epilogue: cosine + running argmax. c ascending + m0 ascending + strict '>'
        // preserves jnp.argmax first-occurrence semantics.
        #pragma unroll
        for (int c = 0; c < 8; c++) {
            int m = m0 + tx * 8 + c;
            float yn = g_yn[b * MM + m];
            #pragma unroll
            for (int r = 0; r < 8; r++) {
                float denom = fmaxf(xn[r] * yn, EPSV);
                float sim = acc[r][c] / denom;
                if (sim > best[r]) { best[r] = sim; bidx[r] = m; }
            }
        }
    }

    // Reduce across the 16 column-threads (lanes share ty within each warp half;
    // xor offsets 1..8 stay inside the 16-lane group).
    #pragma unroll
    for (int r = 0; r < 8; r++) {
        float v = best[r];
        int   id = bidx[r];
        #pragma unroll
        for (int off = 1; off < 16; off <<= 1) {
            float ov = __shfl_xor_sync(0xffffffffu, v, off);
            int   oi = __shfl_xor_sync(0xffffffffu, id, off);
            if (ov > v || (ov == v && oi < id)) { v = ov; id = oi; }
        }
        if (tx == 0) {
            int n = n0 + ty * 8 + r;
            // matched points [B,N,2] first, then confidence [B,N]
            out[((size_t)b * NN + n) * 2 + 0] = pts[((size_t)b * MM + id) * 2 + 0];
            out[((size_t)b * NN + n) * 2 + 1] = pts[((size_t)b * MM + id) * 2 + 1];
            out[(size_t)BB * NN * 2 + (size_t)b * NN + n] = v;
        }
    }
}

extern "C" void kernel_launch(void* const* d_in, const int* in_sizes, int n_in,
                              void* d_out, int out_size) {
    const float* desc_src   = (const float*)d_in[0];
    const float* desc_dst   = (const float*)d_in[1];
    const float* points_dst = (const float*)d_in[2];
    float* out = (float*)d_out;

    // Norms: 2*B*N rows, one warp each, 8 warps per block.
    int total_warps = 2 * BB * NN;                 // 32768
    norms_kernel<<<total_warps / 8, NTHREADS>>>(desc_src, desc_dst);

    dim3 grid(NN / BN, BB);                        // 16 x 8 = 128 CTAs
    match_kernel<<<grid, NTHREADS>>>(desc_src, desc_dst, points_dst, out);
}

// round 3
// speedup vs baseline: 2.5996x; 2.5996x over previous
#include <cuda_runtime.h>
#include <cstdint>
#include <math.h>

#define BB 8
#define NN 2048
#define MM 2048
#define DD 256

#define TPB 256
#define BN  128      // src rows per CTA (MMA M)
#define BMT 128      // dst rows per m-tile (MMA N sweep unit)
#define KC  32       // k per chunk
#define NMT (MM / BMT)          // 16
#define NCHUNK (DD / KC)        // 8
#define TOTC (NMT * NCHUNK)     // 128 chunks

#define LDSTR 36                       // floats per smem row (stride 36 ≡ 4 mod 32 -> conflict-free frags)
#define ATILE (128 * LDSTR * 4)        // 18432 B per tile array
#define BUFB  (2 * ATILE)              // A + B raw fp32 per buffer
#define RED_OFF (2 * BUFB)             // reduction scratch after the two buffers
#define SMEM_TOTAL (2 * BUFB + 2 * 128 * 2 * 4)   // 75776 B

__device__ float g_ixn[BB * NN];   // 1/||src_row||
__device__ float g_iyn[BB * MM];   // 1/||dst_row||

static __device__ __forceinline__ uint32_t smem_u32(const void* p) {
    uint32_t a;
    asm("{ .reg .u64 t; cvta.to.shared.u64 t, %1; cvt.u32.u64 %0, t; }" : "=r"(a) : "l"(p));
    return a;
}
static __device__ __forceinline__ void cpasync16(uint32_t saddr, const void* g) {
    asm volatile("cp.async.cg.shared.global [%0], [%1], 16;" :: "r"(saddr), "l"(g));
}
static __device__ __forceinline__ void cp_commit() {
    asm volatile("cp.async.commit_group;" ::: "memory");
}
template <int N>
static __device__ __forceinline__ void cp_wait() {
    asm volatile("cp.async.wait_group %0;" :: "n"(N) : "memory");
}
// split fp32 into hi/lo tf32 (rna): x ~= hi + lo, |err| <~ 2^-22 |x|
static __device__ __forceinline__ void split1(float x, uint32_t& h, uint32_t& l) {
    asm("cvt.rna.tf32.f32 %0, %1;" : "=r"(h) : "f"(x));
    float r = x - __uint_as_float(h);
    asm("cvt.rna.tf32.f32 %0, %1;" : "=r"(l) : "f"(r));
}
static __device__ __forceinline__ void mma8(float* d, const uint32_t* a, const uint32_t* b) {
    asm volatile(
        "mma.sync.aligned.m16n8k8.row.col.f32.tf32.tf32.f32 "
        "{%0,%1,%2,%3}, {%4,%5,%6,%7}, {%8,%9}, {%0,%1,%2,%3};"
        : "+f"(d[0]), "+f"(d[1]), "+f"(d[2]), "+f"(d[3])
        : "r"(a[0]), "r"(a[1]), "r"(a[2]), "r"(a[3]), "r"(b[0]), "r"(b[1]));
}

// One warp per row: inverse L2 norm over D=256.
__global__ void norms_kernel(const float* __restrict__ src, const float* __restrict__ dst) {
    int warp = (blockIdx.x * blockDim.x + threadIdx.x) >> 5;
    int lane = threadIdx.x & 31;
    const float* p;
    float* o;
    int row;
    if (warp < BB * NN) { p = src; o = g_ixn; row = warp; }
    else                { p = dst; o = g_iyn; row = warp - BB * NN; }
    const float4* v = (const float4*)(p + (size_t)row * DD) + lane * 2;
    float4 a = v[0], b4 = v[1];
    float s = a.x * a.x + a.y * a.y + a.z * a.z + a.w * a.w
            + b4.x * b4.x + b4.y * b4.y + b4.z * b4.z + b4.w * b4.w;
    #pragma unroll
    for (int off = 16; off; off >>= 1) s += __shfl_xor_sync(0xffffffffu, s, off);
    if (lane == 0) o[row] = 1.0f / sqrtf(s);
}

__global__ __launch_bounds__(TPB, 1)
void match_kernel(const float* __restrict__ src, const float* __restrict__ dst,
                  const float* __restrict__ pts, float* __restrict__ out) {
    extern __shared__ char sm[];
    const uint32_t sb = smem_u32(sm);
    const int tid = threadIdx.x;
    const int lane = tid & 31;
    const int wid  = tid >> 5;
    const int gid  = lane >> 2;   // group id (0..7)
    const int tig  = lane & 3;    // thread-in-group
    const int wr   = wid & 3;     // warp row  (rows wr*32 .. +31)
    const int wc   = wid >> 2;    // warp col  (cols wc*64 .. +63)
    const int b  = blockIdx.y;
    const int n0 = blockIdx.x * BN;

    const float* gA  = src + ((size_t)b * NN + n0) * DD;
    const float* gB0 = dst + (size_t)b * MM * DD;

    // issue cp.async for linear chunk cc into buffer q
    auto issue = [&](int cc, int q) {
        const float* gB = gB0 + (size_t)(cc >> 3) * BMT * DD;
        const int kb = (cc & 7) * KC;
        const uint32_t aBase = sb + q * BUFB;
        const uint32_t bBase = aBase + ATILE;
        #pragma unroll
        for (int i = 0; i < 4; i++) {
            int lin = tid + i * TPB;
            int row = lin >> 3, k4 = lin & 7;
            cpasync16(aBase + (row * LDSTR + k4 * 4) * 4, gA + row * DD + kb + k4 * 4);
        }
        #pragma unroll
        for (int i = 0; i < 4; i++) {
            int lin = tid + i * TPB;
            int row = lin >> 3, k4 = lin & 7;
            cpasync16(bBase + (row * LDSTR + k4 * 4) * 4, gB + row * DD + kb + k4 * 4);
        }
        cp_commit();
    };

    float acc[2][8][4];
    #pragma unroll
    for (int i = 0; i < 2; i++)
        #pragma unroll
        for (int j = 0; j < 8; j++)
            #pragma unroll
            for (int k = 0; k < 4; k++) acc[i][j][k] = 0.0f;

    float best[4];
    int   bidx[4];
    #pragma unroll
    for (int j = 0; j < 4; j++) { best[j] = -1e30f; bidx[j] = 0; }

    issue(0, 0);

    #pragma unroll 1
    for (int cc = 0; cc < TOTC; cc++) {
        const int q = cc & 1;
        if (cc + 1 < TOTC) { issue(cc + 1, q ^ 1); cp_wait<1>(); }
        else               { cp_wait<0>(); }
        __syncthreads();

        const float* A  = (const float*)(sm + q * BUFB);
        const float* Bm = (const float*)(sm + q * BUFB + ATILE);

        #pragma unroll
        for (int ks = 0; ks < 4; ks++) {
            // A fragments (hi/lo) for the 2 m16 tiles of this warp row
            uint32_t aH[2][4], aL[2][4];
            #pragma unroll
            for (int mt2 = 0; mt2 < 2; mt2++) {
                int r0 = wr * 32 + mt2 * 16 + gid;
                int kb = ks * 8 + tig;
                split1(A[r0 * LDSTR + kb],             aH[mt2][0], aL[mt2][0]);
                split1(A[(r0 + 8) * LDSTR + kb],       aH[mt2][1], aL[mt2][1]);
                split1(A[r0 * LDSTR + kb + 4],         aH[mt2][2], aL[mt2][2]);
                split1(A[(r0 + 8) * LDSTR + kb + 4],   aH[mt2][3], aL[mt2][3]);
            }
            // B fragments (hi/lo) for the 8 n8 tiles of this warp col
            uint32_t bH[8][2], bL[8][2];
            #pragma unroll
            for (int nt = 0; nt < 8; nt++) {
                int rn = wc * 64 + nt * 8 + gid;
                int kb = ks * 8 + tig;
                split1(Bm[rn * LDSTR + kb],     bH[nt][0], bL[nt][0]);
                split1(Bm[rn * LDSTR + kb + 4], bH[nt][1], bL[nt][1]);
            }
            #pragma unroll
            for (int mt2 = 0; mt2 < 2; mt2++)
                #pragma unroll
                for (int nt = 0; nt < 8; nt++) {
                    mma8(acc[mt2][nt], aH[mt2], bH[nt]);   // hh
                    mma8(acc[mt2][nt], aH[mt2], bL[nt]);   // hl
                    mma8(acc[mt2][nt], aL[mt2], bH[nt]);   // lh
                }
        }

        if ((cc & 7) == 7) {
            // end of m-tile: fold sims into running argmax, reset acc
            const int mt = cc >> 3;
            const int mbase = mt * BMT + wc * 64;
            const float* iy = g_iyn + b * MM + mbase;
            #pragma unroll
            for (int nt = 0; nt < 8; nt++) {
                float2 y2 = *(const float2*)(iy + nt * 8 + 2 * tig);
                int m0 = mbase + nt * 8 + 2 * tig;
                #pragma unroll
                for (int mt2 = 0; mt2 < 2; mt2++) {
                    float v0 = acc[mt2][nt][0] * y2.x;
                    float v1 = acc[mt2][nt][1] * y2.y;
                    float v2 = acc[mt2][nt][2] * y2.x;
                    float v3 = acc[mt2][nt][3] * y2.y;
                    int j0 = mt2 * 2, j1 = mt2 * 2 + 1;
                    if (v0 > best[j0]) { best[j0] = v0; bidx[j0] = m0; }
                    if (v1 > best[j0]) { best[j0] = v1; bidx[j0] = m0 + 1; }
                    if (v2 > best[j1]) { best[j1] = v2; bidx[j1] = m0; }
                    if (v3 > best[j1]) { best[j1] = v3; bidx[j1] = m0 + 1; }
                    acc[mt2][nt][0] = 0.0f; acc[mt2][nt][1] = 0.0f;
                    acc[mt2][nt][2] = 0.0f; acc[mt2][nt][3] = 0.0f;
                }
            }
        }
        __syncthreads();
    }

    // reduce across the 4 lanes of each group (same rows, interleaved cols)
    float* sval = (float*)(sm + RED_OFF);
    int*   sidx = (int*)(sm + RED_OFF + 2 * 128 * 4);
    #pragma unroll
    for (int j = 0; j < 4; j++) {
        float v = best[j];
        int   id = bidx[j];
        #pragma unroll
        for (int off = 1; off < 4; off <<= 1) {
            float ov = __shfl_xor_sync(0xffffffffu, v, off);
            int   oi = __shfl_xor_sync(0xffffffffu, id, off);
            if (ov > v || (ov == v && oi < id)) { v = ov; id = oi; }
        }
        if (tig == 0) {
            int r = wr * 32 + (j >> 1) * 16 + (j & 1) * 8 + gid;   // 0..127
            sval[wc * 128 + r] = v;
            sidx[wc * 128 + r] = id;
        }
    }
    __syncthreads();

    if (tid < 128) {
        int r = tid;
        float v0 = sval[r], v1 = sval[128 + r];
        int i0 = sidx[r], i1 = sidx[128 + r];
        float v = v0;
        int id = i0;
        if (v1 > v0 || (v1 == v0 && i1 < i0)) { v = v1; id = i1; }
        int n = n0 + r;
        float conf = v * g_ixn[b * NN + n];
        size_t ob = (size_t)b * NN + n;
        out[ob * 2]     = pts[((size_t)b * MM + id) * 2];
        out[ob * 2 + 1] = pts[((size_t)b * MM + id) * 2 + 1];
        out[(size_t)BB * NN * 2 + ob] = conf;
    }
}

extern "C" void kernel_launch(void* const* d_in, const int* in_sizes, int n_in,
                              void* d_out, int out_size) {
    const float* desc_src = (const float*)d_in[0];
    const float* desc_dst = (const float*)d_in[1];
    const float* points_dst = (const float*)d_in[2];
    float* out = (float*)d_out;

    cudaFuncSetAttribute(match_kernel, cudaFuncAttributeMaxDynamicSharedMemorySize,
                         SMEM_TOTAL);

    int total_warps = 2 * BB * NN;
    norms_kernel<<<total_warps / 8, TPB>>>(desc_src, desc_dst);

    dim3 grid(NN / BN, BB);   // 16 x 8 = 128 CTAs
    match_kernel<<<grid, TPB, SMEM_TOTAL>>>(desc_src, desc_dst, points_dst, out);
}

// round 4
// speedup vs baseline: 2.7755x; 1.0677x over previous
#include <cuda_runtime.h>
#include <cstdint>
#include <math.h>

#define BB 8
#define NN 2048
#define MM 2048
#define DD 256

#define TPB 256
#define BN  128                 // src rows per CTA (MMA M)
#define BMT 128                 // dst rows per m-tile
#define KC  32                  // k per chunk
#define NMT (MM / BMT)          // 16
#define NCHUNK (DD / KC)        // 8
#define TOTC (NMT * NCHUNK)     // 128 chunks

#define PKF 512                 // packed floats per row: 256 k * (hi+lo)

// smem: row stride 320B (20 x 16B units) -> conflict-free LDS.128 fragments
#define RSB 320
#define ATILEB (128 * RSB)              // 40960 B
#define BUFB   (2 * ATILEB)             // A + B per buffer
#define RED_OFF (2 * BUFB)
#define SMEM_TOTAL (2 * BUFB + 2048)    // 165888 B

__device__ float g_ixn[BB * NN];
__device__ float g_iyn[BB * MM];
__device__ float g_psrc[BB * NN * PKF];   // packed hi/lo tf32, 33.5 MB
__device__ float g_pdst[BB * MM * PKF];

static __device__ __forceinline__ uint32_t smem_u32(const void* p) {
    uint32_t a;
    asm("{ .reg .u64 t; cvta.to.shared.u64 t, %1; cvt.u32.u64 %0, t; }" : "=r"(a) : "l"(p));
    return a;
}
static __device__ __forceinline__ void cpasync16(uint32_t saddr, const void* g) {
    asm volatile("cp.async.cg.shared.global [%0], [%1], 16;" :: "r"(saddr), "l"(g));
}
static __device__ __forceinline__ void cp_commit() {
    asm volatile("cp.async.commit_group;" ::: "memory");
}
template <int N>
static __device__ __forceinline__ void cp_wait() {
    asm volatile("cp.async.wait_group %0;" :: "n"(N) : "memory");
}
static __device__ __forceinline__ void split1(float x, float& h, float& l) {
    uint32_t hh;
    asm("cvt.rna.tf32.f32 %0, %1;" : "=r"(hh) : "f"(x));
    h = __uint_as_float(hh);
    float r = x - h;
    uint32_t ll;
    asm("cvt.rna.tf32.f32 %0, %1;" : "=r"(ll) : "f"(r));
    l = __uint_as_float(ll);
}
static __device__ __forceinline__ void mma8(float* d, const uint32_t* a, const uint32_t* b) {
    asm volatile(
        "mma.sync.aligned.m16n8k8.row.col.f32.tf32.tf32.f32 "
        "{%0,%1,%2,%3}, {%4,%5,%6,%7}, {%8,%9}, {%0,%1,%2,%3};"
        : "+f"(d[0]), "+f"(d[1]), "+f"(d[2]), "+f"(d[3])
        : "r"(a[0]), "r"(a[1]), "r"(a[2]), "r"(a[3]), "r"(b[0]), "r"(b[1]));
}

// Prepass: one warp per row. Computes inverse L2 norm AND writes the packed
// hi/lo tf32 layout: unit u (16B) of chunk c = {hi_k, hi_{k+4}, lo_k, lo_{k+4}}
// with ks=u/4, g=u%4, k = c*32 + ks*8 + g  (exactly MMA fragment order).
__global__ __launch_bounds__(TPB)
void pack_kernel(const float* __restrict__ src, const float* __restrict__ dst) {
    __shared__ float stage[8][264];
    const int wid = threadIdx.x >> 5, lane = threadIdx.x & 31;
    int row = blockIdx.x * 8 + wid;
    const float* p;
    float* onorm;
    float* pk;
    int r;
    if (row < BB * NN) { p = src; onorm = g_ixn; pk = g_psrc; r = row; }
    else               { p = dst; onorm = g_iyn; pk = g_pdst; r = row - BB * NN; }

    const float4* v = (const float4*)(p + (size_t)r * DD);
    float4 x0 = v[lane * 2], x1 = v[lane * 2 + 1];
    *(float4*)&stage[wid][lane * 8]     = x0;
    *(float4*)&stage[wid][lane * 8 + 4] = x1;
    float s = x0.x * x0.x + x0.y * x0.y + x0.z * x0.z + x0.w * x0.w
            + x1.x * x1.x + x1.y * x1.y + x1.z * x1.z + x1.w * x1.w;
    #pragma unroll
    for (int off = 16; off; off >>= 1) s += __shfl_xor_sync(0xffffffffu, s, off);
    if (lane == 0) onorm[r] = 1.0f / sqrtf(s);
    __syncwarp();

    float4* outp = (float4*)(pk + (size_t)r * PKF);
    #pragma unroll
    for (int i = 0; i < 4; i++) {
        int u = lane + 32 * i;          // 0..127 16B units
        int c = u >> 4, q = u & 15;
        int ks = q >> 2, g = q & 3;
        int k = c * 32 + ks * 8 + g;
        float h0, l0, h1, l1;
        split1(stage[wid][k],     h0, l0);
        split1(stage[wid][k + 4], h1, l1);
        outp[u] = make_float4(h0, h1, l0, l1);
    }
}

__global__ __launch_bounds__(TPB, 1)
void match_kernel(const float* __restrict__ pts, float* __restrict__ out) {
    extern __shared__ char sm[];
    const uint32_t sb = smem_u32(sm);
    const int tid = threadIdx.x;
    const int lane = tid & 31;
    const int wid  = tid >> 5;
    const int gid  = lane >> 2;
    const int tig  = lane & 3;
    const int wr   = wid & 3;    // rows wr*32..+31
    const int wc   = wid >> 1 & 1 ? 1 : wid >> 2;  // placeholder, fixed below
    const int wcc  = wid >> 2;   // warp col (0/1): cols wcc*64..+63
    const int b  = blockIdx.y;
    const int n0 = blockIdx.x * BN;
    (void)wc;

    const float* gAp = g_psrc + ((size_t)b * NN + n0) * PKF;
    const float* gBp = g_pdst + (size_t)b * MM * PKF;

    auto issue = [&](int cc, int q) {
        const float* gB = gBp + (size_t)(cc >> 3) * BMT * PKF;
        const int ch = cc & 7;
        const uint32_t aBase = sb + q * BUFB;
        const uint32_t bBase = aBase + ATILEB;
        #pragma unroll
        for (int i = 0; i < 8; i++) {
            int lin = tid + i * TPB;
            int row = lin >> 4, u = lin & 15;
            cpasync16(aBase + row * RSB + u * 16, gAp + (size_t)row * PKF + ch * 64 + u * 4);
        }
        #pragma unroll
        for (int i = 0; i < 8; i++) {
            int lin = tid + i * TPB;
            int row = lin >> 4, u = lin & 15;
            cpasync16(bBase + row * RSB + u * 16, gB + (size_t)row * PKF + ch * 64 + u * 4);
        }
        cp_commit();
    };

    float acc[2][8][4];
    #pragma unroll
    for (int i = 0; i < 2; i++)
        #pragma unroll
        for (int j = 0; j < 8; j++)
            #pragma unroll
            for (int k = 0; k < 4; k++) acc[i][j][k] = 0.0f;

    float best[4];
    int   bidx[4];
    #pragma unroll
    for (int j = 0; j < 4; j++) { best[j] = -1e30f; bidx[j] = 0; }

    issue(0, 0);

    #pragma unroll 1
    for (int cc = 0; cc < TOTC; cc++) {
        const int q = cc & 1;
        if (cc + 1 < TOTC) { issue(cc + 1, q ^ 1); cp_wait<1>(); }
        else               { cp_wait<0>(); }
        __syncthreads();

        const char* A  = sm + q * BUFB;
        const char* Bm = A + ATILEB;

        #pragma unroll
        for (int ks = 0; ks < 4; ks++) {
            const int uoff = (ks * 4 + tig) * 16;
            // A fragments: one LDS.128 per row gives {hi_k, hi_k4, lo_k, lo_k4}
            uint32_t aH[2][4], aL[2][4];
            #pragma unroll
            for (int mt2 = 0; mt2 < 2; mt2++) {
                int r0 = wr * 32 + mt2 * 16 + gid;
                float4 v0 = *(const float4*)(A + r0 * RSB + uoff);
                float4 v1 = *(const float4*)(A + (r0 + 8) * RSB + uoff);
                aH[mt2][0] = __float_as_uint(v0.x);
                aH[mt2][1] = __float_as_uint(v1.x);
                aH[mt2][2] = __float_as_uint(v0.y);
                aH[mt2][3] = __float_as_uint(v1.y);
                aL[mt2][0] = __float_as_uint(v0.z);
                aL[mt2][1] = __float_as_uint(v1.z);
                aL[mt2][2] = __float_as_uint(v0.w);
                aL[mt2][3] = __float_as_uint(v1.w);
            }
            uint32_t bH[8][2], bL[8][2];
            #pragma unroll
            for (int nt = 0; nt < 8; nt++) {
                int rn = wcc * 64 + nt * 8 + gid;
                float4 v = *(const float4*)(Bm + rn * RSB + uoff);
                bH[nt][0] = __float_as_uint(v.x);
                bH[nt][1] = __float_as_uint(v.y);
                bL[nt][0] = __float_as_uint(v.z);
                bL[nt][1] = __float_as_uint(v.w);
            }
            #pragma unroll
            for (int mt2 = 0; mt2 < 2; mt2++)
                #pragma unroll
                for (int nt = 0; nt < 8; nt++) {
                    mma8(acc[mt2][nt], aH[mt2], bH[nt]);   // hh
                    mma8(acc[mt2][nt], aH[mt2], bL[nt]);   // hl
                    mma8(acc[mt2][nt], aL[mt2], bH[nt]);   // lh
                }
        }

        if ((cc & 7) == 7) {
            const int mt = cc >> 3;
            const int mbase = mt * BMT + wcc * 64;
            const float* iy = g_iyn + b * MM + mbase;
            #pragma unroll
            for (int nt = 0; nt < 8; nt++) {
                float2 y2 = *(const float2*)(iy + nt * 8 + 2 * tig);
                int m0 = mbase + nt * 8 + 2 * tig;
                #pragma unroll
                for (int mt2 = 0; mt2 < 2; mt2++) {
                    float v0 = acc[mt2][nt][0] * y2.x;
                    float v1 = acc[mt2][nt][1] * y2.y;
                    float v2 = acc[mt2][nt][2] * y2.x;
                    float v3 = acc[mt2][nt][3] * y2.y;
                    int j0 = mt2 * 2, j1 = mt2 * 2 + 1;
                    if (v0 > best[j0]) { best[j0] = v0; bidx[j0] = m0; }
                    if (v1 > best[j0]) { best[j0] = v1; bidx[j0] = m0 + 1; }
                    if (v2 > best[j1]) { best[j1] = v2; bidx[j1] = m0; }
                    if (v3 > best[j1]) { best[j1] = v3; bidx[j1] = m0 + 1; }
                    acc[mt2][nt][0] = 0.0f; acc[mt2][nt][1] = 0.0f;
                    acc[mt2][nt][2] = 0.0f; acc[mt2][nt][3] = 0.0f;
                }
            }
        }
        __syncthreads();
    }

    // reduce across the 4 lanes of each group, then across the two warp cols
    float* sval = (float*)(sm + RED_OFF);
    int*   sidx = (int*)(sm + RED_OFF + 2 * 128 * 4);
    #pragma unroll
    for (int j = 0; j < 4; j++) {
        float v = best[j];
        int   id = bidx[j];
        #pragma unroll
        for (int off = 1; off < 4; off <<= 1) {
            float ov = __shfl_xor_sync(0xffffffffu, v, off);
            int   oi = __shfl_xor_sync(0xffffffffu, id, off);
            if (ov > v || (ov == v && oi < id)) { v = ov; id = oi; }
        }
        if (tig == 0) {
            int r = wr * 32 + (j >> 1) * 16 + (j & 1) * 8 + gid;
            sval[wcc * 128 + r] = v;
            sidx[wcc * 128 + r] = id;
        }
    }
    __syncthreads();

    if (tid < 128) {
        int r = tid;
        float v0 = sval[r], v1 = sval[128 + r];
        int i0 = sidx[r], i1 = sidx[128 + r];
        float v = v0;
        int id = i0;
        if (v1 > v0 || (v1 == v0 && i1 < i0)) { v = v1; id = i1; }
        int n = n0 + r;
        float conf = v * g_ixn[b * NN + n];
        size_t ob = (size_t)b * NN + n;
        out[ob * 2]     = pts[((size_t)b * MM + id) * 2];
        out[ob * 2 + 1] = pts[((size_t)b * MM + id) * 2 + 1];
        out[(size_t)BB * NN * 2 + ob] = conf;
    }
}

extern "C" void kernel_launch(void* const* d_in, const int* in_sizes, int n_in,
                              void* d_out, int out_size) {
    const float* desc_src = (const float*)d_in[0];
    const float* desc_dst = (const float*)d_in[1];
    const float* points_dst = (const float*)d_in[2];
    float* out = (float*)d_out;

    cudaFuncSetAttribute(match_kernel, cudaFuncAttributeMaxDynamicSharedMemorySize,
                         SMEM_TOTAL);

    pack_kernel<<<(2 * BB * NN) / 8, TPB>>>(desc_src, desc_dst);

    dim3 grid(NN / BN, BB);   // 16 x 8 = 128 CTAs
    match_kernel<<<grid, TPB, SMEM_TOTAL>>>(points_dst, out);
}